// round 12
// baseline (speedup 1.0000x reference)
#include <cuda_runtime.h>
#include <cuda_bf16.h>
#include <cstdint>

#define N_NODES 50000
#define N_EDGES 600000
#define HID     128
#define N_GRAPHS 32
#define D_OUT   3
#define SCAN_BLOCKS ((N_NODES + 255) / 256)   // 196

typedef unsigned long long u64;

// ---------------- scratch (device globals; no allocs) ----------------
__device__ int   g_cnt[N_NODES];
__device__ int   g_rowptr[N_NODES + 1];
__device__ int   g_cursor[N_NODES];
__device__ int   g_col[N_EDGES];
__device__ int   g_bsum[SCAN_BLOCKS];
__device__ int   g_tick;
__device__ __nv_bfloat16 g_P[(size_t)N_NODES * HID];   // messages, bf16
__device__ float g_bufA[(size_t)N_NODES * HID];
__device__ float g_bufB[(size_t)N_NODES * HID];
__device__ float g_gsum[N_GRAPHS * HID];
__device__ float g_gcnt[N_GRAPHS];

// ---------------- helpers ----------------
__device__ __forceinline__ u64 pack_dup(float a) {
    u64 r;
    asm("mov.b64 %0, {%1,%1};" : "=l"(r) : "f"(a));
    return r;
}
__device__ __forceinline__ float2 unpack2(u64 v) {
    float2 r;
    asm("mov.b64 {%0,%1}, %2;" : "=f"(r.x), "=f"(r.y) : "l"(v));
    return r;
}
__device__ __forceinline__ void ffma2(u64& acc, u64 a, u64 b) {
    asm("fma.rn.f32x2 %0, %1, %2, %0;" : "+l"(acc) : "l"(a), "l"(b));
}
__device__ __forceinline__ uint32_t f2tf32(float f) {
    uint32_t u;
    asm("cvt.rna.tf32.f32 %0, %1;" : "=r"(u) : "f"(f));
    return u;
}
__device__ __forceinline__ void mma_tf32(float* c, uint32_t a0, uint32_t a1,
                                         uint32_t a2, uint32_t a3,
                                         uint32_t b0, uint32_t b1) {
    asm volatile(
        "mma.sync.aligned.m16n8k8.row.col.f32.tf32.tf32.f32 "
        "{%0,%1,%2,%3}, {%4,%5,%6,%7}, {%8,%9}, {%0,%1,%2,%3};"
        : "+f"(c[0]), "+f"(c[1]), "+f"(c[2]), "+f"(c[3])
        : "r"(a0), "r"(a1), "r"(a2), "r"(a3), "r"(b0), "r"(b1));
}

// =================================================================
// Hybrid dual GEMM:
//   out1 = A@W1^T + bias    [fp32, FFMA2 on fma pipe]
//   out2 = bf16(A@W2^T)     [tf32 mma.sync on tensor pipe, fp32 accum]
// 128x128 tile, 256 threads.
// sA:  fp32, R4 layout: float4 word (row,c4) at row*128 + ((c4^(row&7))<<2)
// sW1: fp32, R7 layout: (k,c4) at k*128 + ((c4 ^ ((k>>2)&31))<<2)
// sW2: tf32 words, R4 layout: (n,k) at n*128 + (k ^ ((n&3)<<2))
// =================================================================
__global__ void __launch_bounds__(256, 1)
gemm_dual(const float* __restrict__ A,
          const float* __restrict__ W1, const float* __restrict__ W2,
          const float* __restrict__ bias,
          float* __restrict__ out1, __nv_bfloat16* __restrict__ out2, int M) {
    extern __shared__ float smem[];
    float* sA   = smem;
    float* sW1  = smem + 16384;
    float* sW2f = smem + 32768;

    int tid = threadIdx.x;
    int tx = tid & 15, ty = tid >> 4;       // FFMA2 microtile coords
    int lane = tid & 31, wid = tid >> 5;    // MMA coords
    int sub = wid;
    int m0 = blockIdx.x * 128;
    int r7 = lane >> 2;                     // MMA row-in-group
    int tq = lane & 3;                      // MMA thread-in-group
    int mrow = wid * 16 + r7;

    // ---- stage A (R4 swizzle) ----
    for (int i = tid; i < 4096; i += 256) {
        int row = i >> 5, c4 = i & 31;
        int grow = m0 + row;
        float4 a = make_float4(0.f, 0.f, 0.f, 0.f);
        if (grow < M) a = *(const float4*)(A + (size_t)grow * 128 + c4 * 4);
        *(float4*)(sA + row * 128 + ((c4 ^ (row & 7)) << 2)) = a;
    }
    // ---- stage W1 (R7 swizzle) ----
    #pragma unroll
    for (int it = 0; it < 16; it++) {
        int col = it * 8 + sub;
        int c4 = col >> 2, cl = col & 3;
        float4 v1 = *(const float4*)(W1 + col * 128 + (lane << 2));
        float vv1[4] = {v1.x, v1.y, v1.z, v1.w};
        #pragma unroll
        for (int i = 0; i < 4; i++) {
            int k = (lane << 2) + i;     // (k>>2)&31 == lane
            sW1[k * 128 + ((c4 ^ lane) << 2) + cl] = vv1[i];
        }
    }
    // ---- stage W2 as tf32 (R4 swizzle, hi only) ----
    for (int i = tid; i < 4096; i += 256) {
        int n = i >> 5, c4 = i & 31;
        float4 w = *(const float4*)(W2 + n * 128 + c4 * 4);
        float ww[4] = {w.x, w.y, w.z, w.w};
        #pragma unroll
        for (int j = 0; j < 4; j++) {
            int k = c4 * 4 + j;
            sW2f[n * 128 + (k ^ ((n & 3) << 2))] = __uint_as_float(f2tf32(ww[j]));
        }
    }
    __syncthreads();

    u64 acc1[8][4];
    float acc2[16][4];
    #pragma unroll
    for (int r = 0; r < 8; r++)
        #pragma unroll
        for (int c = 0; c < 4; c++) acc1[r][c] = 0ull;
    #pragma unroll
    for (int n = 0; n < 16; n++)
        #pragma unroll
        for (int c = 0; c < 4; c++) acc2[n][c] = 0.f;

    #pragma unroll 1
    for (int q2 = 0; q2 < 16; q2++) {
        // ---- MMA k8 block (tensor pipe; R4-proven fragment indexing) ----
        {
            int k0 = q2 * 8;
            int kc = k0 + tq;
            float af0 = sA[mrow * 128 + (kc ^ (r7 << 2))];
            float af1 = sA[(mrow + 8) * 128 + (kc ^ (r7 << 2))];
            float af2 = sA[mrow * 128 + ((kc + 4) ^ (r7 << 2))];
            float af3 = sA[(mrow + 8) * 128 + ((kc + 4) ^ (r7 << 2))];
            uint32_t ah0 = f2tf32(af0), ah1 = f2tf32(af1);
            uint32_t ah2 = f2tf32(af2), ah3 = f2tf32(af3);
            #pragma unroll
            for (int n = 0; n < 16; n++) {
                int nn = n * 8 + r7;
                int sw = (nn & 3) << 2;
                uint32_t b0 = __float_as_uint(sW2f[nn * 128 + (kc ^ sw)]);
                uint32_t b1 = __float_as_uint(sW2f[nn * 128 + ((kc + 4) ^ sw)]);
                mma_tf32(acc2[n], ah0, ah1, ah2, ah3, b0, b1);
            }
        }
        // ---- FFMA2 partial for q = 2*q2, 2*q2+1 (fma pipe) ----
        #pragma unroll
        for (int h = 0; h < 2; h++) {
            int q = q2 * 2 + h;
            float4 af4[8];
            #pragma unroll
            for (int r = 0; r < 8; r++)
                af4[r] = *(const float4*)(sA + (ty * 8 + r) * 128 + ((q ^ r) << 2));
            #pragma unroll
            for (int j = 0; j < 4; j++) {
                int k = q * 4 + j;
                const float* w1r = sW1 + k * 128;
                ulonglong2 p0 = *(const ulonglong2*)(w1r + ((((tx << 1)    ) ^ q) << 2));
                ulonglong2 p1 = *(const ulonglong2*)(w1r + ((((tx << 1) | 1) ^ q) << 2));
                u64 b1v[4] = {p0.x, p0.y, p1.x, p1.y};
                u64 a2[8];
                #pragma unroll
                for (int r = 0; r < 8; r++)
                    a2[r] = pack_dup(((const float*)&af4[r])[j]);
                #pragma unroll
                for (int r = 0; r < 8; r++)
                    #pragma unroll
                    for (int c = 0; c < 4; c++)
                        ffma2(acc1[r][c], a2[r], b1v[c]);
            }
        }
    }

    // ---- epilogue: partial (fp32 + bias) ----
    float bv[8];
    #pragma unroll
    for (int j = 0; j < 8; j++) bv[j] = bias[tx * 8 + j];

    #pragma unroll
    for (int r = 0; r < 8; r++) {
        int grow = m0 + ty * 8 + r;
        if (grow < M) {
            float o[8];
            #pragma unroll
            for (int c = 0; c < 4; c++) {
                float2 v = unpack2(acc1[r][c]);
                o[2 * c]     = v.x + bv[2 * c];
                o[2 * c + 1] = v.y + bv[2 * c + 1];
            }
            float4* d1 = (float4*)(out1 + (size_t)grow * 128 + tx * 8);
            d1[0] = make_float4(o[0], o[1], o[2], o[3]);
            d1[1] = make_float4(o[4], o[5], o[6], o[7]);
        }
    }
    // ---- epilogue: P -> bf16 (R4-proven fragment->matrix mapping) ----
    {
        int row0 = m0 + wid * 16 + r7;
        #pragma unroll
        for (int n = 0; n < 16; n++) {
            int col = n * 8 + tq * 2;
            if (row0 < M) {
                __nv_bfloat162 h0 = __float22bfloat162_rn(
                    make_float2(acc2[n][0], acc2[n][1]));
                *(uint32_t*)(out2 + (size_t)row0 * 128 + col) = *(uint32_t*)&h0;
            }
            if (row0 + 8 < M) {
                __nv_bfloat162 h1 = __float22bfloat162_rn(
                    make_float2(acc2[n][2], acc2[n][3]));
                *(uint32_t*)(out2 + (size_t)(row0 + 8) * 128 + col) = *(uint32_t*)&h1;
            }
        }
    }
}

// =================================================================
// Single GEMM (lin1): out1 = relu(A@W1^T + bias)  — exact R7 path
// =================================================================
__global__ void __launch_bounds__(256, 1)
gemm_single(const float* __restrict__ A, const float* __restrict__ W1,
            const float* __restrict__ bias, float* __restrict__ out1, int M) {
    extern __shared__ float smem[];
    float* sIn = smem;
    float* sW1 = smem + 16384;

    int tid = threadIdx.x;
    int tx = tid & 15, ty = tid >> 4;
    int lane = tid & 31, sub = tid >> 5;
    int m0 = blockIdx.x * 128;

    #pragma unroll
    for (int it = 0; it < 16; it++) {
        int row = it * 8 + sub;
        int grow = m0 + row;
        float4 v = make_float4(0.f, 0.f, 0.f, 0.f);
        if (grow < M) v = *(const float4*)(A + (size_t)grow * 128 + lane * 4);
        *(float4*)(sIn + row * 128 + lane * 4) = v;
    }
    #pragma unroll
    for (int it = 0; it < 16; it++) {
        int col = it * 8 + sub;
        int c4 = col >> 2, cl = col & 3;
        float4 v1 = *(const float4*)(W1 + col * 128 + (lane << 2));
        float vv1[4] = {v1.x, v1.y, v1.z, v1.w};
        #pragma unroll
        for (int i = 0; i < 4; i++) {
            int k = (lane << 2) + i;
            sW1[k * 128 + ((c4 ^ lane) << 2) + cl] = vv1[i];
        }
    }
    __syncthreads();

    u64 acc1[8][4];
    #pragma unroll
    for (int r = 0; r < 8; r++)
        #pragma unroll
        for (int c = 0; c < 4; c++) acc1[r][c] = 0ull;

    #pragma unroll 4
    for (int k = 0; k < 128; k++) {
        u64 a2[8];
        #pragma unroll
        for (int r = 0; r < 8; r++)
            a2[r] = pack_dup(sIn[(ty * 8 + r) * 128 + k]);
        int swz = (k >> 2) & 31;
        const float* w1r = sW1 + k * 128;
        ulonglong2 p0 = *(const ulonglong2*)(w1r + ((((tx << 1)    ) ^ swz) << 2));
        ulonglong2 p1 = *(const ulonglong2*)(w1r + ((((tx << 1) | 1) ^ swz) << 2));
        u64 b1v[4] = {p0.x, p0.y, p1.x, p1.y};
        #pragma unroll
        for (int r = 0; r < 8; r++)
            #pragma unroll
            for (int c = 0; c < 4; c++)
                ffma2(acc1[r][c], a2[r], b1v[c]);
    }

    float bv[8];
    #pragma unroll
    for (int j = 0; j < 8; j++) bv[j] = bias[tx * 8 + j];

    #pragma unroll
    for (int r = 0; r < 8; r++) {
        int grow = m0 + ty * 8 + r;
        if (grow < M) {
            float o[8];
            #pragma unroll
            for (int c = 0; c < 4; c++) {
                float2 v = unpack2(acc1[r][c]);
                o[2 * c]     = fmaxf(v.x + bv[2 * c], 0.f);
                o[2 * c + 1] = fmaxf(v.y + bv[2 * c + 1], 0.f);
            }
            float4* d1 = (float4*)(out1 + (size_t)grow * 128 + tx * 8);
            d1[0] = make_float4(o[0], o[1], o[2], o[3]);
            d1[1] = make_float4(o[4], o[5], o[6], o[7]);
        }
    }
}

// ---------------- CSR build ----------------
__global__ void zero_kernel() {
    int i = blockIdx.x * blockDim.x + threadIdx.x;
    if (i < N_NODES) g_cnt[i] = 0;
    if (i < N_GRAPHS * HID) g_gsum[i] = 0.0f;
    if (i < N_GRAPHS) g_gcnt[i] = 0.0f;
    if (i == 0) g_tick = 0;
}

__global__ void hist_kernel(const int* __restrict__ dst) {
    int e4 = blockIdx.x * blockDim.x + threadIdx.x;
    if (e4 < N_EDGES / 4) {
        int4 d = ((const int4*)dst)[e4];
        atomicAdd(&g_cnt[d.x], 1);
        atomicAdd(&g_cnt[d.y], 1);
        atomicAdd(&g_cnt[d.z], 1);
        atomicAdd(&g_cnt[d.w], 1);
    }
}

__global__ void scan1_kernel() {
    __shared__ int ws[8];
    int tid = threadIdx.x, lane = tid & 31, w = tid >> 5;
    int i = blockIdx.x * 256 + tid;
    int v = (i < N_NODES) ? g_cnt[i] : 0;
    #pragma unroll
    for (int off = 16; off > 0; off >>= 1)
        v += __shfl_down_sync(0xffffffffu, v, off);
    if (lane == 0) ws[w] = v;
    __syncthreads();
    if (tid == 0) {
        int s = 0;
        #pragma unroll
        for (int j = 0; j < 8; j++) s += ws[j];
        g_bsum[blockIdx.x] = s;
    }
}

__global__ void scan3m_kernel() {
    __shared__ int ws[8];
    __shared__ int s_boff;
    int tid = threadIdx.x, lane = tid & 31, w = tid >> 5;

    int v = (tid < SCAN_BLOCKS) ? g_bsum[tid] : 0;
    int x = v;
    #pragma unroll
    for (int off = 1; off < 32; off <<= 1) {
        int t = __shfl_up_sync(0xffffffffu, x, off);
        if (lane >= off) x += t;
    }
    if (lane == 31) ws[w] = x;
    __syncthreads();
    if (w == 0 && lane < 8) {
        int y = ws[lane];
        #pragma unroll
        for (int off = 1; off < 8; off <<= 1) {
            int t = __shfl_up_sync(0xffu, y, off);
            if (lane >= off) y += t;
        }
        ws[lane] = y;
    }
    __syncthreads();
    int incl = x + (w > 0 ? ws[w - 1] : 0);
    if (tid == blockIdx.x) s_boff = incl - v;
    if (blockIdx.x == 0 && tid == 0) g_rowptr[0] = 0;
    __syncthreads();

    int i = blockIdx.x * 256 + tid;
    int c = (i < N_NODES) ? g_cnt[i] : 0;
    int y = c;
    #pragma unroll
    for (int off = 1; off < 32; off <<= 1) {
        int t = __shfl_up_sync(0xffffffffu, y, off);
        if (lane >= off) y += t;
    }
    if (lane == 31) ws[w] = y;
    __syncthreads();
    if (w == 0 && lane < 8) {
        int z = ws[lane];
        #pragma unroll
        for (int off = 1; off < 8; off <<= 1) {
            int t = __shfl_up_sync(0xffu, z, off);
            if (lane >= off) z += t;
        }
        ws[lane] = z;
    }
    __syncthreads();
    int inc2 = y + (w > 0 ? ws[w - 1] : 0) + s_boff;
    if (i < N_NODES) {
        g_rowptr[i + 1] = inc2;
        g_cursor[i] = inc2 - c;
    }
}

__global__ void fill_kernel(const int* __restrict__ src,
                            const int* __restrict__ dst) {
    int e4 = blockIdx.x * blockDim.x + threadIdx.x;
    if (e4 < N_EDGES / 4) {
        int4 d = ((const int4*)dst)[e4];
        int4 s = ((const int4*)src)[e4];
        g_col[atomicAdd(&g_cursor[d.x], 1)] = s.x;
        g_col[atomicAdd(&g_cursor[d.y], 1)] = s.y;
        g_col[atomicAdd(&g_cursor[d.z], 1)] = s.z;
        g_col[atomicAdd(&g_cursor[d.w], 1)] = s.w;
    }
}

// ------- fused aggregation: out = relu(partial + mean_{j in N(i)} P_j) -------
__global__ void aggf_kernel(const __nv_bfloat16* __restrict__ P,
                            const float* __restrict__ partial,
                            float* __restrict__ out) {
    int node = (blockIdx.x * blockDim.x + threadIdx.x) >> 5;
    int lane = threadIdx.x & 31;
    if (node >= N_NODES) return;
    int s = g_rowptr[node];
    int e = g_rowptr[node + 1];
    float4 acc = make_float4(0.f, 0.f, 0.f, 0.f);
    for (int j = s; j < e; j++) {
        int sn = g_col[j];
        uint2 v = *((const uint2*)(P + (size_t)sn * HID) + lane);
        float2 f0 = __bfloat1622float2(*reinterpret_cast<__nv_bfloat162*>(&v.x));
        float2 f1 = __bfloat1622float2(*reinterpret_cast<__nv_bfloat162*>(&v.y));
        acc.x += f0.x; acc.y += f0.y; acc.z += f1.x; acc.w += f1.y;
    }
    int deg = e - s;
    float inv = 1.0f / (float)(deg > 0 ? deg : 1);
    float4 p = *(const float4*)(partial + (size_t)node * HID + lane * 4);
    float4 o;
    o.x = fmaxf(p.x + acc.x * inv, 0.f);
    o.y = fmaxf(p.y + acc.y * inv, 0.f);
    o.z = fmaxf(p.z + acc.z * inv, 0.f);
    o.w = fmaxf(p.w + acc.w * inv, 0.f);
    *(float4*)(out + (size_t)node * HID + lane * 4) = o;
}

// ---------------- pooling + fused final (ticketed last block) ----------------
__global__ void pool_kernel(const float* __restrict__ h,
                            const int* __restrict__ batch,
                            const float* __restrict__ fcW,
                            const float* __restrict__ fcb,
                            float* __restrict__ out) {
    int t = threadIdx.x;
    int r0 = blockIdx.x * 128;
    int r1 = r0 + 128; if (r1 > N_NODES) r1 = N_NODES;
    if (r0 < N_NODES) {
        int gprev = batch[r0];
        float acc = 0.0f, cacc = 0.0f;
        for (int r = r0; r < r1; r++) {
            int g = batch[r];
            if (g != gprev) {
                atomicAdd(&g_gsum[gprev * HID + t], acc);
                if (t == 0) atomicAdd(&g_gcnt[gprev], cacc);
                acc = 0.0f; cacc = 0.0f; gprev = g;
            }
            acc += h[(size_t)r * HID + t];
            cacc += 1.0f;
        }
        atomicAdd(&g_gsum[gprev * HID + t], acc);
        if (t == 0) atomicAdd(&g_gcnt[gprev], cacc);
    }
    __threadfence();
    __shared__ int s_last;
    if (t == 0) s_last = (atomicAdd(&g_tick, 1) == (int)gridDim.x - 1);
    __syncthreads();
    if (s_last && t < N_GRAPHS * D_OUT) {
        int g = t / D_OUT, o = t % D_OUT;
        float cnt = g_gcnt[g];
        float inv = 1.0f / fmaxf(cnt, 1.0f);
        float s = 0.0f;
        #pragma unroll 8
        for (int k = 0; k < HID; k++)
            s += g_gsum[g * HID + k] * fcW[o * HID + k];
        out[g * D_OUT + o] = s * inv + fcb[o];
    }
}

// ---------------- launch ----------------
extern "C" void kernel_launch(void* const* d_in, const int* in_sizes, int n_in,
                              void* d_out, int out_size) {
    const float* x    = (const float*)d_in[0];
    const float* Wl0  = (const float*)d_in[1];
    const float* bl0  = (const float*)d_in[2];
    const float* Wr0  = (const float*)d_in[3];
    const float* W1   = (const float*)d_in[4];
    const float* b1   = (const float*)d_in[5];
    const float* Wl1  = (const float*)d_in[6];
    const float* bl1  = (const float*)d_in[7];
    const float* Wr1  = (const float*)d_in[8];
    const float* fcW  = (const float*)d_in[9];
    const float* fcb  = (const float*)d_in[10];
    const int*   ei   = (const int*)d_in[11];     // int64 ref -> int32 harness
    const int*   batch= (const int*)d_in[12];
    float*       out  = (float*)d_out;

    const int* src = ei;
    const int* dst = ei + N_EDGES;

    void *pP = nullptr, *pA = nullptr, *pB = nullptr;
    cudaGetSymbolAddress(&pP, g_P);
    cudaGetSymbolAddress(&pA, g_bufA);
    cudaGetSymbolAddress(&pB, g_bufB);
    __nv_bfloat16* P = (__nv_bfloat16*)pP;
    float* bufA = (float*)pA;
    float* bufB = (float*)pB;

    const int SMEM_D = 3 * 16384 * sizeof(float);   // 196608
    const int SMEM_S = 2 * 16384 * sizeof(float);   // 131072
    cudaFuncSetAttribute(gemm_dual,   cudaFuncAttributeMaxDynamicSharedMemorySize, SMEM_D);
    cudaFuncSetAttribute(gemm_single, cudaFuncAttributeMaxDynamicSharedMemorySize, SMEM_S);

    // side stream + events, created ONCE on first (non-captured) call
    static cudaStream_t s2 = nullptr;
    static cudaEvent_t evFork = nullptr, evJoin = nullptr;
    if (s2 == nullptr) {
        cudaStreamCreateWithFlags(&s2, cudaStreamNonBlocking);
        cudaEventCreateWithFlags(&evFork, cudaEventDisableTiming);
        cudaEventCreateWithFlags(&evJoin, cudaEventDisableTiming);
    }

    int gemm_blocks = (N_NODES + 127) / 128;   // 391

    // fork: CSR build on s2, conv0 dual GEMM on main stream (independent)
    cudaEventRecord(evFork, 0);
    cudaStreamWaitEvent(s2, evFork, 0);

    zero_kernel<<<(N_NODES + 255) / 256, 256, 0, s2>>>();
    hist_kernel<<<(N_EDGES / 4 + 255) / 256, 256, 0, s2>>>(dst);
    scan1_kernel<<<SCAN_BLOCKS, 256, 0, s2>>>();

    // conv0 on main stream (submission position 4 for ncu)
    gemm_dual<<<gemm_blocks, 256, SMEM_D>>>(x, Wr0, Wl0, bl0, bufA, P, N_NODES);

    scan3m_kernel<<<SCAN_BLOCKS, 256, 0, s2>>>();
    fill_kernel<<<(N_EDGES / 4 + 255) / 256, 256, 0, s2>>>(src, dst);

    // join: aggf needs CSR + conv0 outputs
    cudaEventRecord(evJoin, s2);
    cudaStreamWaitEvent(0, evJoin, 0);

    // conv0 combine: bufB = relu(partial + agg(P))
    aggf_kernel<<<(N_NODES + 7) / 8, 256>>>(P, bufA, bufB);

    // lin1: bufA = relu(bufB@W1^T + b1)
    gemm_single<<<gemm_blocks, 256, SMEM_S>>>(bufB, W1, b1, bufA, N_NODES);

    // conv1: partial = bufA@Wr1^T + bl1 (bufB), P = bf16(bufA@Wl1^T)
    gemm_dual<<<gemm_blocks, 256, SMEM_D>>>(bufA, Wr1, Wl1, bl1, bufB, P, N_NODES);
    aggf_kernel<<<(N_NODES + 7) / 8, 256>>>(P, bufB, bufA);

    // pool + fused final (ticketed)
    pool_kernel<<<(N_NODES + 127) / 128, 128>>>(bufA, batch, fcW, fcb, out);
}

// round 13
// speedup vs baseline: 1.1121x; 1.1121x over previous
#include <cuda_runtime.h>
#include <cuda_bf16.h>
#include <cstdint>

#define N_NODES 50000
#define N_EDGES 600000
#define HID     128
#define N_GRAPHS 32
#define D_OUT   3
#define SCAN_BLOCKS ((N_NODES + 255) / 256)   // 196

typedef unsigned long long u64;

// ---------------- scratch (device globals; no allocs) ----------------
__device__ int   g_cnt[N_NODES];
__device__ int   g_rowptr[N_NODES + 1];
__device__ int   g_cursor[N_NODES];
__device__ int   g_col[N_EDGES];
__device__ int   g_bsum[SCAN_BLOCKS];
__device__ int   g_tick;
__device__ __nv_bfloat16 g_P[(size_t)N_NODES * HID];   // messages, bf16
__device__ float g_bufA[(size_t)N_NODES * HID];
__device__ float g_bufB[(size_t)N_NODES * HID];
__device__ float g_gsum[N_GRAPHS * HID];
__device__ float g_gcnt[N_GRAPHS];

// ---------------- f32x2 helpers ----------------
__device__ __forceinline__ u64 pack_dup(float a) {
    u64 r;
    asm("mov.b64 %0, {%1,%1};" : "=l"(r) : "f"(a));
    return r;
}
__device__ __forceinline__ float2 unpack2(u64 v) {
    float2 r;
    asm("mov.b64 {%0,%1}, %2;" : "=f"(r.x), "=f"(r.y) : "l"(v));
    return r;
}
__device__ __forceinline__ void ffma2(u64& acc, u64 a, u64 b) {
    asm("fma.rn.f32x2 %0, %1, %2, %0;" : "+l"(acc) : "l"(a), "l"(b));
}

// ---- R7-proven staging helpers (256 threads) ----
// sIn row-major [row*128 + k]
__device__ __forceinline__ void stage_A(float* sIn, const float* __restrict__ A,
                                        int m0, int M, int lane, int sub) {
    #pragma unroll
    for (int it = 0; it < 16; it++) {
        int row = it * 8 + sub;
        int grow = m0 + row;
        float4 v = make_float4(0.f, 0.f, 0.f, 0.f);
        if (grow < M) v = *(const float4*)(A + (size_t)grow * 128 + lane * 4);
        *(float4*)(sIn + row * 128 + lane * 4) = v;
    }
}
// sW k-major, float4 XOR-swizzle: (k, c4) at k*128 + ((c4 ^ ((k>>2)&31))<<2)
__device__ __forceinline__ void stage_W(float* sW, const float* __restrict__ W,
                                        int lane, int sub) {
    #pragma unroll
    for (int it = 0; it < 16; it++) {
        int col = it * 8 + sub;
        int c4 = col >> 2, cl = col & 3;
        float4 v = *(const float4*)(W + col * 128 + (lane << 2));
        float vv[4] = {v.x, v.y, v.z, v.w};
        #pragma unroll
        for (int i = 0; i < 4; i++) {
            int k = (lane << 2) + i;     // (k>>2)&31 == lane
            sW[k * 128 + ((c4 ^ lane) << 2) + cl] = vv[i];
        }
    }
}

// ---- R7-proven FFMA2 k-loops (tx = tid&15 col-group, ty = tid>>4 row-group) ----
__device__ __forceinline__ void kloop_single(const float* sIn, const float* sW1,
                                             u64 acc1[8][4], int tx, int ty) {
    #pragma unroll 4
    for (int k = 0; k < 128; k++) {
        u64 a2[8];
        #pragma unroll
        for (int r = 0; r < 8; r++)
            a2[r] = pack_dup(sIn[(ty * 8 + r) * 128 + k]);
        int swz = (k >> 2) & 31;
        const float* w1r = sW1 + k * 128;
        ulonglong2 p0 = *(const ulonglong2*)(w1r + ((((tx << 1)    ) ^ swz) << 2));
        ulonglong2 p1 = *(const ulonglong2*)(w1r + ((((tx << 1) | 1) ^ swz) << 2));
        u64 b1v[4] = {p0.x, p0.y, p1.x, p1.y};
        #pragma unroll
        for (int r = 0; r < 8; r++)
            #pragma unroll
            for (int c = 0; c < 4; c++)
                ffma2(acc1[r][c], a2[r], b1v[c]);
    }
}
__device__ __forceinline__ void kloop_dual(const float* sIn, const float* sW1,
                                           const float* sW2,
                                           u64 acc1[8][4], u64 acc2[8][4],
                                           int tx, int ty) {
    #pragma unroll 4
    for (int k = 0; k < 128; k++) {
        u64 a2[8];
        #pragma unroll
        for (int r = 0; r < 8; r++)
            a2[r] = pack_dup(sIn[(ty * 8 + r) * 128 + k]);
        int swz = (k >> 2) & 31;
        const float* w1r = sW1 + k * 128;
        ulonglong2 p0 = *(const ulonglong2*)(w1r + ((((tx << 1)    ) ^ swz) << 2));
        ulonglong2 p1 = *(const ulonglong2*)(w1r + ((((tx << 1) | 1) ^ swz) << 2));
        u64 b1v[4] = {p0.x, p0.y, p1.x, p1.y};
        #pragma unroll
        for (int r = 0; r < 8; r++)
            #pragma unroll
            for (int c = 0; c < 4; c++)
                ffma2(acc1[r][c], a2[r], b1v[c]);
        const float* w2r = sW2 + k * 128;
        ulonglong2 q0 = *(const ulonglong2*)(w2r + ((((tx << 1)    ) ^ swz) << 2));
        ulonglong2 q1 = *(const ulonglong2*)(w2r + ((((tx << 1) | 1) ^ swz) << 2));
        u64 b2v[4] = {q0.x, q0.y, q1.x, q1.y};
        #pragma unroll
        for (int r = 0; r < 8; r++)
            #pragma unroll
            for (int c = 0; c < 4; c++)
                ffma2(acc2[r][c], a2[r], b2v[c]);
    }
}

// ---- dual epilogue: out1 fp32 (+bias), out2 bf16 ----
__device__ __forceinline__ void epi_dual(u64 acc1[8][4], u64 acc2[8][4],
                                         const float* __restrict__ bias,
                                         float* __restrict__ out1,
                                         __nv_bfloat16* __restrict__ out2,
                                         int m0, int M, int tx, int ty) {
    float bv[8];
    #pragma unroll
    for (int j = 0; j < 8; j++) bv[j] = bias[tx * 8 + j];
    #pragma unroll
    for (int r = 0; r < 8; r++) {
        int grow = m0 + ty * 8 + r;
        if (grow < M) {
            float o[8];
            #pragma unroll
            for (int c = 0; c < 4; c++) {
                float2 v = unpack2(acc1[r][c]);
                o[2 * c]     = v.x + bv[2 * c];
                o[2 * c + 1] = v.y + bv[2 * c + 1];
            }
            float4* d1 = (float4*)(out1 + (size_t)grow * 128 + tx * 8);
            d1[0] = make_float4(o[0], o[1], o[2], o[3]);
            d1[1] = make_float4(o[4], o[5], o[6], o[7]);
            __nv_bfloat162 h[4];
            #pragma unroll
            for (int c = 0; c < 4; c++) {
                float2 v = unpack2(acc2[r][c]);
                h[c] = __float22bfloat162_rn(v);
            }
            uint4 pk;
            pk.x = *(uint32_t*)&h[0];
            pk.y = *(uint32_t*)&h[1];
            pk.z = *(uint32_t*)&h[2];
            pk.w = *(uint32_t*)&h[3];
            *(uint4*)(out2 + (size_t)grow * 128 + tx * 8) = pk;
        }
    }
}

// =================================================================
// conv0 dual GEMM (exact R7): out1 = A@W1^T+bias [fp32], out2 = bf16(A@W2^T)
// =================================================================
__global__ void __launch_bounds__(256, 1)
gemm_dual(const float* __restrict__ A,
          const float* __restrict__ W1, const float* __restrict__ W2,
          const float* __restrict__ bias,
          float* __restrict__ out1, __nv_bfloat16* __restrict__ out2, int M) {
    extern __shared__ float smem[];
    float* sIn = smem;
    float* sW1 = smem + 16384;
    float* sW2 = smem + 32768;

    int tid = threadIdx.x;
    int tx = tid & 15, ty = tid >> 4;
    int lane = tid & 31, sub = tid >> 5;
    int m0 = blockIdx.x * 128;

    stage_A(sIn, A, m0, M, lane, sub);
    stage_W(sW1, W1, lane, sub);
    stage_W(sW2, W2, lane, sub);
    __syncthreads();

    u64 acc1[8][4], acc2[8][4];
    #pragma unroll
    for (int r = 0; r < 8; r++)
        #pragma unroll
        for (int c = 0; c < 4; c++) { acc1[r][c] = 0ull; acc2[r][c] = 0ull; }

    kloop_dual(sIn, sW1, sW2, acc1, acc2, tx, ty);
    epi_dual(acc1, acc2, bias, out1, out2, m0, M, tx, ty);
}

// =================================================================
// fused lin1 + conv1:
//   phase 1: h = relu(A@W1^T + b1)  (R7 single loop) -> written back to sIn
//   phase 2: out1 = h@Wr^T + blr [fp32], out2 = bf16(h@Wl^T)  (R7 dual loop)
// =================================================================
__global__ void __launch_bounds__(256, 1)
gemm_fused(const float* __restrict__ A,
           const float* __restrict__ W1, const float* __restrict__ b1,
           const float* __restrict__ Wr, const float* __restrict__ Wl,
           const float* __restrict__ blr,
           float* __restrict__ out1, __nv_bfloat16* __restrict__ out2, int M) {
    extern __shared__ float smem[];
    float* sIn = smem;
    float* sW1 = smem + 16384;
    float* sW2 = smem + 32768;

    int tid = threadIdx.x;
    int tx = tid & 15, ty = tid >> 4;
    int lane = tid & 31, sub = tid >> 5;
    int m0 = blockIdx.x * 128;

    // ---- phase 1: lin1 ----
    stage_A(sIn, A, m0, M, lane, sub);
    stage_W(sW1, W1, lane, sub);
    __syncthreads();

    u64 acc1[8][4], acc2[8][4];
    #pragma unroll
    for (int r = 0; r < 8; r++)
        #pragma unroll
        for (int c = 0; c < 4; c++) acc1[r][c] = 0ull;

    kloop_single(sIn, sW1, acc1, tx, ty);
    __syncthreads();   // everyone's reads of sIn / sW1 complete

    // write h = relu(acc1 + b1) back into sIn (same row-major layout)
    {
        float bv1[8];
        #pragma unroll
        for (int j = 0; j < 8; j++) bv1[j] = b1[tx * 8 + j];
        #pragma unroll
        for (int r = 0; r < 8; r++) {
            float o[8];
            #pragma unroll
            for (int c = 0; c < 4; c++) {
                float2 v = unpack2(acc1[r][c]);
                o[2 * c]     = fmaxf(v.x + bv1[2 * c], 0.f);
                o[2 * c + 1] = fmaxf(v.y + bv1[2 * c + 1], 0.f);
            }
            float4* d = (float4*)(sIn + (ty * 8 + r) * 128 + tx * 8);
            d[0] = make_float4(o[0], o[1], o[2], o[3]);
            d[1] = make_float4(o[4], o[5], o[6], o[7]);
        }
    }
    stage_W(sW1, Wr, lane, sub);
    stage_W(sW2, Wl, lane, sub);
    __syncthreads();

    // ---- phase 2: conv1 dual from h ----
    #pragma unroll
    for (int r = 0; r < 8; r++)
        #pragma unroll
        for (int c = 0; c < 4; c++) { acc1[r][c] = 0ull; acc2[r][c] = 0ull; }

    kloop_dual(sIn, sW1, sW2, acc1, acc2, tx, ty);
    epi_dual(acc1, acc2, blr, out1, out2, m0, M, tx, ty);
}

// ---------------- CSR build ----------------
__global__ void zero_kernel() {
    int i = blockIdx.x * blockDim.x + threadIdx.x;
    if (i < N_NODES) g_cnt[i] = 0;
    if (i < N_GRAPHS * HID) g_gsum[i] = 0.0f;
    if (i < N_GRAPHS) g_gcnt[i] = 0.0f;
    if (i == 0) g_tick = 0;
}

__global__ void hist_kernel(const int* __restrict__ dst) {
    int e4 = blockIdx.x * blockDim.x + threadIdx.x;
    if (e4 < N_EDGES / 4) {
        int4 d = ((const int4*)dst)[e4];
        atomicAdd(&g_cnt[d.x], 1);
        atomicAdd(&g_cnt[d.y], 1);
        atomicAdd(&g_cnt[d.z], 1);
        atomicAdd(&g_cnt[d.w], 1);
    }
}

__global__ void scan1_kernel() {
    __shared__ int ws[8];
    int tid = threadIdx.x, lane = tid & 31, w = tid >> 5;
    int i = blockIdx.x * 256 + tid;
    int v = (i < N_NODES) ? g_cnt[i] : 0;
    #pragma unroll
    for (int off = 16; off > 0; off >>= 1)
        v += __shfl_down_sync(0xffffffffu, v, off);
    if (lane == 0) ws[w] = v;
    __syncthreads();
    if (tid == 0) {
        int s = 0;
        #pragma unroll
        for (int j = 0; j < 8; j++) s += ws[j];
        g_bsum[blockIdx.x] = s;
    }
}

__global__ void scan3m_kernel() {
    __shared__ int ws[8];
    __shared__ int s_boff;
    int tid = threadIdx.x, lane = tid & 31, w = tid >> 5;

    int v = (tid < SCAN_BLOCKS) ? g_bsum[tid] : 0;
    int x = v;
    #pragma unroll
    for (int off = 1; off < 32; off <<= 1) {
        int t = __shfl_up_sync(0xffffffffu, x, off);
        if (lane >= off) x += t;
    }
    if (lane == 31) ws[w] = x;
    __syncthreads();
    if (w == 0 && lane < 8) {
        int y = ws[lane];
        #pragma unroll
        for (int off = 1; off < 8; off <<= 1) {
            int t = __shfl_up_sync(0xffu, y, off);
            if (lane >= off) y += t;
        }
        ws[lane] = y;
    }
    __syncthreads();
    int incl = x + (w > 0 ? ws[w - 1] : 0);
    if (tid == blockIdx.x) s_boff = incl - v;
    if (blockIdx.x == 0 && tid == 0) g_rowptr[0] = 0;
    __syncthreads();

    int i = blockIdx.x * 256 + tid;
    int c = (i < N_NODES) ? g_cnt[i] : 0;
    int y = c;
    #pragma unroll
    for (int off = 1; off < 32; off <<= 1) {
        int t = __shfl_up_sync(0xffffffffu, y, off);
        if (lane >= off) y += t;
    }
    if (lane == 31) ws[w] = y;
    __syncthreads();
    if (w == 0 && lane < 8) {
        int z = ws[lane];
        #pragma unroll
        for (int off = 1; off < 8; off <<= 1) {
            int t = __shfl_up_sync(0xffu, z, off);
            if (lane >= off) z += t;
        }
        ws[lane] = z;
    }
    __syncthreads();
    int inc2 = y + (w > 0 ? ws[w - 1] : 0) + s_boff;
    if (i < N_NODES) {
        g_rowptr[i + 1] = inc2;
        g_cursor[i] = inc2 - c;
    }
}

__global__ void fill_kernel(const int* __restrict__ src,
                            const int* __restrict__ dst) {
    int e4 = blockIdx.x * blockDim.x + threadIdx.x;
    if (e4 < N_EDGES / 4) {
        int4 d = ((const int4*)dst)[e4];
        int4 s = ((const int4*)src)[e4];
        g_col[atomicAdd(&g_cursor[d.x], 1)] = s.x;
        g_col[atomicAdd(&g_cursor[d.y], 1)] = s.y;
        g_col[atomicAdd(&g_cursor[d.z], 1)] = s.z;
        g_col[atomicAdd(&g_cursor[d.w], 1)] = s.w;
    }
}

// ------- fused aggregation: out = relu(partial + mean_{j in N(i)} P_j) -------
__global__ void aggf_kernel(const __nv_bfloat16* __restrict__ P,
                            const float* __restrict__ partial,
                            float* __restrict__ out) {
    int node = (blockIdx.x * blockDim.x + threadIdx.x) >> 5;
    int lane = threadIdx.x & 31;
    if (node >= N_NODES) return;
    int s = g_rowptr[node];
    int e = g_rowptr[node + 1];
    float4 acc = make_float4(0.f, 0.f, 0.f, 0.f);
    for (int j = s; j < e; j++) {
        int sn = g_col[j];
        uint2 v = *((const uint2*)(P + (size_t)sn * HID) + lane);
        float2 f0 = __bfloat1622float2(*reinterpret_cast<__nv_bfloat162*>(&v.x));
        float2 f1 = __bfloat1622float2(*reinterpret_cast<__nv_bfloat162*>(&v.y));
        acc.x += f0.x; acc.y += f0.y; acc.z += f1.x; acc.w += f1.y;
    }
    int deg = e - s;
    float inv = 1.0f / (float)(deg > 0 ? deg : 1);
    float4 p = *(const float4*)(partial + (size_t)node * HID + lane * 4);
    float4 o;
    o.x = fmaxf(p.x + acc.x * inv, 0.f);
    o.y = fmaxf(p.y + acc.y * inv, 0.f);
    o.z = fmaxf(p.z + acc.z * inv, 0.f);
    o.w = fmaxf(p.w + acc.w * inv, 0.f);
    *(float4*)(out + (size_t)node * HID + lane * 4) = o;
}

// ---------------- pooling + fused final (ticketed last block) ----------------
__global__ void pool_kernel(const float* __restrict__ h,
                            const int* __restrict__ batch,
                            const float* __restrict__ fcW,
                            const float* __restrict__ fcb,
                            float* __restrict__ out) {
    int t = threadIdx.x;
    int r0 = blockIdx.x * 128;
    int r1 = r0 + 128; if (r1 > N_NODES) r1 = N_NODES;
    if (r0 < N_NODES) {
        int gprev = batch[r0];
        float acc = 0.0f, cacc = 0.0f;
        for (int r = r0; r < r1; r++) {
            int g = batch[r];
            if (g != gprev) {
                atomicAdd(&g_gsum[gprev * HID + t], acc);
                if (t == 0) atomicAdd(&g_gcnt[gprev], cacc);
                acc = 0.0f; cacc = 0.0f; gprev = g;
            }
            acc += h[(size_t)r * HID + t];
            cacc += 1.0f;
        }
        atomicAdd(&g_gsum[gprev * HID + t], acc);
        if (t == 0) atomicAdd(&g_gcnt[gprev], cacc);
    }
    __threadfence();
    __shared__ int s_last;
    if (t == 0) s_last = (atomicAdd(&g_tick, 1) == (int)gridDim.x - 1);
    __syncthreads();
    if (s_last && t < N_GRAPHS * D_OUT) {
        int g = t / D_OUT, o = t % D_OUT;
        float cnt = g_gcnt[g];
        float inv = 1.0f / fmaxf(cnt, 1.0f);
        float s = 0.0f;
        #pragma unroll 8
        for (int k = 0; k < HID; k++)
            s += g_gsum[g * HID + k] * fcW[o * HID + k];
        out[g * D_OUT + o] = s * inv + fcb[o];
    }
}

// ---------------- launch ----------------
extern "C" void kernel_launch(void* const* d_in, const int* in_sizes, int n_in,
                              void* d_out, int out_size) {
    const float* x    = (const float*)d_in[0];
    const float* Wl0  = (const float*)d_in[1];
    const float* bl0  = (const float*)d_in[2];
    const float* Wr0  = (const float*)d_in[3];
    const float* W1   = (const float*)d_in[4];
    const float* b1   = (const float*)d_in[5];
    const float* Wl1  = (const float*)d_in[6];
    const float* bl1  = (const float*)d_in[7];
    const float* Wr1  = (const float*)d_in[8];
    const float* fcW  = (const float*)d_in[9];
    const float* fcb  = (const float*)d_in[10];
    const int*   ei   = (const int*)d_in[11];     // int64 ref -> int32 harness
    const int*   batch= (const int*)d_in[12];
    float*       out  = (float*)d_out;

    const int* src = ei;
    const int* dst = ei + N_EDGES;

    void *pP = nullptr, *pA = nullptr, *pB = nullptr;
    cudaGetSymbolAddress(&pP, g_P);
    cudaGetSymbolAddress(&pA, g_bufA);
    cudaGetSymbolAddress(&pB, g_bufB);
    __nv_bfloat16* P = (__nv_bfloat16*)pP;
    float* bufA = (float*)pA;
    float* bufB = (float*)pB;

    const int SMEM_D = 3 * 16384 * sizeof(float);   // 196608
    cudaFuncSetAttribute(gemm_dual,  cudaFuncAttributeMaxDynamicSharedMemorySize, SMEM_D);
    cudaFuncSetAttribute(gemm_fused, cudaFuncAttributeMaxDynamicSharedMemorySize, SMEM_D);

    // side stream + events, created ONCE on first (non-captured) call
    static cudaStream_t s2 = nullptr;
    static cudaEvent_t evFork = nullptr, evJoin = nullptr;
    if (s2 == nullptr) {
        cudaStreamCreateWithFlags(&s2, cudaStreamNonBlocking);
        cudaEventCreateWithFlags(&evFork, cudaEventDisableTiming);
        cudaEventCreateWithFlags(&evJoin, cudaEventDisableTiming);
    }

    int gemm_blocks = (N_NODES + 127) / 128;   // 391

    // fork: CSR build on s2, conv0 dual GEMM on main stream (independent)
    cudaEventRecord(evFork, 0);
    cudaStreamWaitEvent(s2, evFork, 0);

    zero_kernel<<<(N_NODES + 255) / 256, 256, 0, s2>>>();
    hist_kernel<<<(N_EDGES / 4 + 255) / 256, 256, 0, s2>>>(dst);
    scan1_kernel<<<SCAN_BLOCKS, 256, 0, s2>>>();

    // conv0 on main stream (submission position 4 for ncu):
    // partial = x@Wr0^T + bl0 -> bufA, P = bf16(x@Wl0^T)
    gemm_dual<<<gemm_blocks, 256, SMEM_D>>>(x, Wr0, Wl0, bl0, bufA, P, N_NODES);

    scan3m_kernel<<<SCAN_BLOCKS, 256, 0, s2>>>();
    fill_kernel<<<(N_EDGES / 4 + 255) / 256, 256, 0, s2>>>(src, dst);

    // join: aggf needs CSR + conv0 outputs
    cudaEventRecord(evJoin, s2);
    cudaStreamWaitEvent(0, evJoin, 0);

    // conv0 combine: bufB = relu(partial + agg(P))
    aggf_kernel<<<(N_NODES + 7) / 8, 256>>>(P, bufA, bufB);

    // fused lin1+conv1: h = relu(bufB@W1^T+b1) (in smem);
    // partial = h@Wr1^T + bl1 -> bufA, P = bf16(h@Wl1^T)
    gemm_fused<<<gemm_blocks, 256, SMEM_D>>>(bufB, W1, b1, Wr1, Wl1, bl1, bufA, P, N_NODES);

    // conv1 combine: bufB = relu(partial + agg(P))
    aggf_kernel<<<(N_NODES + 7) / 8, 256>>>(P, bufA, bufB);

    // pool + fused final (ticketed)
    pool_kernel<<<(N_NODES + 127) / 128, 128>>>(bufB, batch, fcW, fcb, out);
}